// round 1
// baseline (speedup 1.0000x reference)
#include <cuda_runtime.h>
#include <math.h>

#define NB   4
#define TT   1024
#define HH   8
#define DD   64
#define DMOD 512
#define DFFV 1024
#define NLAY 6
#define ROWS (NB * TT)   // 4096

// ---------------- scratch (static device globals; no allocation) -------------
__device__ float g_h  [ROWS * DMOD];       // 8 MB
__device__ float g_qkv[ROWS * 3 * DMOD];   // 24 MB
__device__ float g_att[ROWS * DMOD];       // 8 MB
__device__ float g_ff1[ROWS * DFFV];       // 16 MB
__device__ float g_ff2[ROWS * DMOD];       // 8 MB

// ---------------- embedding + positional encoding ----------------------------
__global__ void embed_kernel(const int* __restrict__ x, const float* __restrict__ emb)
{
    int row = blockIdx.x;            // 0..4095 == n*T + t
    int t   = row & (TT - 1);
    int tok = x[row];
    const float* e = emb + (size_t)tok * DMOD;
    for (int i = threadIdx.x; i < DMOD; i += blockDim.x) {
        // angle_rate = 10000^(-2*floor(i/2)/512); double precision for trig accuracy
        double expo = -2.0 * (double)(i >> 1) / (double)DMOD;
        double ang  = (double)t * pow(10000.0, expo);
        float  p    = (i & 1) ? (float)cos(ang) : (float)sin(ang);
        g_h[(size_t)row * DMOD + i] = e[i] * 22.62741699796952f + p;  // sqrt(512)
    }
}

// ---------------- tiled fp32 GEMM: C = A[MxK] * B[KxN] + bias, opt ReLU ------
template<bool RELU>
__global__ __launch_bounds__(256)
void gemm_kernel(const float* __restrict__ A, const float* __restrict__ B,
                 const float* __restrict__ bias, float* __restrict__ C,
                 int M, int N, int K)
{
    const int BM = 128, BN = 64, BK = 16, TM = 8, TN = 4;
    __shared__ float As[BK][BM + 4];
    __shared__ float Bs[BK][BN];

    int tid = threadIdx.x;
    int tx  = tid & 15;        // 0..15  -> N
    int ty  = tid >> 4;        // 0..15  -> M
    int bm  = blockIdx.y * BM;
    int bn  = blockIdx.x * BN;

    float acc[TM][TN];
#pragma unroll
    for (int i = 0; i < TM; ++i)
#pragma unroll
        for (int j = 0; j < TN; ++j) acc[i][j] = 0.f;

    for (int k0 = 0; k0 < K; k0 += BK) {
        // load A tile (128x16) as float4 along K, transpose into As[k][m]
#pragma unroll
        for (int jj = 0; jj < 2; ++jj) {
            int idx = tid + jj * 256;          // 0..511
            int m   = idx >> 2;
            int k4  = (idx & 3) << 2;
            float4 v = *(const float4*)(A + (size_t)(bm + m) * K + k0 + k4);
            As[k4 + 0][m] = v.x; As[k4 + 1][m] = v.y;
            As[k4 + 2][m] = v.z; As[k4 + 3][m] = v.w;
        }
        // load B tile (16x64), row-major float4
        {
            int k  = tid >> 4;                 // 0..15
            int n4 = (tid & 15) << 2;
            *(float4*)&Bs[k][n4] = *(const float4*)(B + (size_t)(k0 + k) * N + bn + n4);
        }
        __syncthreads();

#pragma unroll
        for (int k = 0; k < BK; ++k) {
            float a[TM], b[TN];
#pragma unroll
            for (int i = 0; i < TM; ++i) a[i] = As[k][ty * TM + i];
#pragma unroll
            for (int j = 0; j < TN; ++j) b[j] = Bs[k][tx * TN + j];
#pragma unroll
            for (int i = 0; i < TM; ++i)
#pragma unroll
                for (int j = 0; j < TN; ++j)
                    acc[i][j] = fmaf(a[i], b[j], acc[i][j]);
        }
        __syncthreads();
    }

    // epilogue: bias (+ ReLU), vectorized float4 store
    int ncol = bn + tx * TN;
    float4 bv = *(const float4*)(bias + ncol);
#pragma unroll
    for (int i = 0; i < TM; ++i) {
        int m = bm + ty * TM + i;
        float4 v;
        v.x = acc[i][0] + bv.x; v.y = acc[i][1] + bv.y;
        v.z = acc[i][2] + bv.z; v.w = acc[i][3] + bv.w;
        if (RELU) {
            v.x = fmaxf(v.x, 0.f); v.y = fmaxf(v.y, 0.f);
            v.z = fmaxf(v.z, 0.f); v.w = fmaxf(v.w, 0.f);
        }
        *(float4*)(C + (size_t)m * N + ncol) = v;
    }
}

// ---------------- flash-style causal attention --------------------------------
// grid: (T/128, N*H); block: 128 threads; one thread per query row.
__global__ __launch_bounds__(128)
void attn_kernel()
{
    __shared__ float Ks[64][64];
    __shared__ float Vs[64][64];

    int tid = threadIdx.x;
    int nh  = blockIdx.y;
    int n   = nh >> 3;
    int hh  = nh & 7;
    int qrow = blockIdx.x * 128 + tid;        // 0..1023 within T

    const size_t base_nk = (size_t)n * TT * 1536 + hh * 192;  // + t*1536 + d*3 + {0,1,2}

    // q, prescaled by 1/sqrt(D)
    float4 qq[16];
    {
        const float* qp = g_qkv + base_nk + (size_t)qrow * 1536;
#pragma unroll
        for (int d4 = 0; d4 < 16; ++d4) {
            qq[d4].x = qp[(d4 * 4 + 0) * 3] * 0.125f;
            qq[d4].y = qp[(d4 * 4 + 1) * 3] * 0.125f;
            qq[d4].z = qp[(d4 * 4 + 2) * 3] * 0.125f;
            qq[d4].w = qp[(d4 * 4 + 3) * 3] * 0.125f;
        }
    }
    float4 oo[16];
#pragma unroll
    for (int d4 = 0; d4 < 16; ++d4) oo[d4] = make_float4(0.f, 0.f, 0.f, 0.f);
    float mval = -INFINITY, lsum = 0.f;

    int ntiles = blockIdx.x * 2 + 2;          // key tiles of 64 covering causal range

#pragma unroll 1
    for (int kt = 0; kt < ntiles; ++kt) {
        __syncthreads();
#pragma unroll
        for (int i = 0; i < 32; ++i) {        // 64*64 / 128 threads
            int idx = tid + i * 128;
            int j = idx >> 6, d = idx & 63;
            const float* kvp = g_qkv + base_nk + (size_t)(kt * 64 + j) * 1536 + d * 3;
            Ks[j][d] = kvp[1];
            Vs[j][d] = kvp[2];
        }
        __syncthreads();

        if (kt * 64 <= qrow) {
#pragma unroll 1
            for (int half = 0; half < 2; ++half) {
                int j0 = half * 32;
                float s[32];
                float tmax = -INFINITY;
#pragma unroll
                for (int j = 0; j < 32; ++j) {
                    const float4* kr = (const float4*)(&Ks[j0 + j][0]);
                    float a = 0.f;
#pragma unroll
                    for (int d4 = 0; d4 < 16; ++d4) {
                        float4 kv = kr[d4];
                        a = fmaf(qq[d4].x, kv.x, a);
                        a = fmaf(qq[d4].y, kv.y, a);
                        a = fmaf(qq[d4].z, kv.z, a);
                        a = fmaf(qq[d4].w, kv.w, a);
                    }
                    s[j] = ((kt * 64 + j0 + j) <= qrow) ? a : -INFINITY;
                    tmax = fmaxf(tmax, s[j]);
                }
                if (tmax > -INFINITY) {
                    float newm = fmaxf(mval, tmax);
                    float corr = expf(mval - newm);   // exp(-inf)=0 on first update
                    lsum *= corr;
#pragma unroll
                    for (int d4 = 0; d4 < 16; ++d4) {
                        oo[d4].x *= corr; oo[d4].y *= corr;
                        oo[d4].z *= corr; oo[d4].w *= corr;
                    }
#pragma unroll
                    for (int j = 0; j < 32; ++j) {
                        float p = expf(s[j] - newm);
                        lsum += p;
                        const float4* vr = (const float4*)(&Vs[j0 + j][0]);
#pragma unroll
                        for (int d4 = 0; d4 < 16; ++d4) {
                            float4 vv = vr[d4];
                            oo[d4].x = fmaf(p, vv.x, oo[d4].x);
                            oo[d4].y = fmaf(p, vv.y, oo[d4].y);
                            oo[d4].z = fmaf(p, vv.z, oo[d4].z);
                            oo[d4].w = fmaf(p, vv.w, oo[d4].w);
                        }
                    }
                    mval = newm;
                }
            }
        }
    }

    float inv = 1.f / lsum;
    float* op = g_att + ((size_t)(n * TT + qrow)) * DMOD + hh * DD;
#pragma unroll
    for (int d4 = 0; d4 < 16; ++d4) {
        float4 v;
        v.x = oo[d4].x * inv; v.y = oo[d4].y * inv;
        v.z = oo[d4].z * inv; v.w = oo[d4].w * inv;
        *(float4*)(op + d4 * 4) = v;
    }
}

// ---------------- fused residual add + LayerNorm ------------------------------
// grid: 4096 rows; block: 256 threads, 2 elements each (DM=512)
__global__ __launch_bounds__(256)
void add_ln_kernel(const float* __restrict__ a, const float* __restrict__ b,
                   const float* __restrict__ gamma, const float* __restrict__ beta,
                   float* __restrict__ out)
{
    int row = blockIdx.x;
    int tid = threadIdx.x;
    const float* ar = a + (size_t)row * DMOD;
    const float* br = b + (size_t)row * DMOD;

    float x0 = ar[tid]       + br[tid];
    float x1 = ar[tid + 256] + br[tid + 256];

    float sum = x0 + x1;
    float sq  = x0 * x0 + x1 * x1;
#pragma unroll
    for (int off = 16; off; off >>= 1) {
        sum += __shfl_xor_sync(0xffffffffu, sum, off);
        sq  += __shfl_xor_sync(0xffffffffu, sq,  off);
    }
    __shared__ float s1[8], s2[8];
    int wid = tid >> 5, lane = tid & 31;
    if (lane == 0) { s1[wid] = sum; s2[wid] = sq; }
    __syncthreads();
    float S = 0.f, Q = 0.f;
#pragma unroll
    for (int i = 0; i < 8; ++i) { S += s1[i]; Q += s2[i]; }

    float mean = S * (1.f / DMOD);
    float var  = Q * (1.f / DMOD) - mean * mean;
    float rstd = 1.f / sqrtf(var + 1e-3f);

    out[(size_t)row * DMOD + tid]       = gamma[tid]       * (x0 - mean) * rstd + beta[tid];
    out[(size_t)row * DMOD + tid + 256] = gamma[tid + 256] * (x1 - mean) * rstd + beta[tid + 256];
}

// ---------------- launch ------------------------------------------------------
extern "C" void kernel_launch(void* const* d_in, const int* in_sizes, int n_in,
                              void* d_out, int out_size)
{
    const int*   x     = (const int*)  d_in[0];
    const float* emb   = (const float*)d_in[1];
    const float* Wqkv  = (const float*)d_in[2];
    const float* bqkv  = (const float*)d_in[3];
    const float* Wff   = (const float*)d_in[4];
    const float* bff   = (const float*)d_in[5];
    const float* Wo    = (const float*)d_in[6];
    const float* bo    = (const float*)d_in[7];
    const float* g1    = (const float*)d_in[8];
    const float* beta1 = (const float*)d_in[9];
    const float* g2    = (const float*)d_in[10];
    const float* beta2 = (const float*)d_in[11];
    float* out = (float*)d_out;

    float *h, *qkv, *att, *ff1, *ff2;
    cudaGetSymbolAddress((void**)&h,   g_h);
    cudaGetSymbolAddress((void**)&qkv, g_qkv);
    cudaGetSymbolAddress((void**)&att, g_att);
    cudaGetSymbolAddress((void**)&ff1, g_ff1);
    cudaGetSymbolAddress((void**)&ff2, g_ff2);

    embed_kernel<<<ROWS, 128>>>(x, emb);

    for (int l = 0; l < NLAY; ++l) {
        // QKV projection: [4096,512] @ [512,1536] + b
        gemm_kernel<false><<<dim3(1536 / 64, ROWS / 128), 256>>>(
            h, Wqkv + (size_t)l * DMOD * 3 * DMOD, bqkv + (size_t)l * 3 * DMOD,
            qkv, ROWS, 3 * DMOD, DMOD);

        // causal flash attention -> g_att
        attn_kernel<<<dim3(TT / 128, NB * HH), 128>>>();

        // h = LN(h + att)
        add_ln_kernel<<<ROWS, 256>>>(h, att, g1 + (size_t)l * DMOD, beta1 + (size_t)l * DMOD, h);

        // FF1: relu([4096,512] @ [512,1024] + b)
        gemm_kernel<true><<<dim3(DFFV / 64, ROWS / 128), 256>>>(
            h, Wff + (size_t)l * DMOD * DFFV, bff + (size_t)l * DFFV,
            ff1, ROWS, DFFV, DMOD);

        // FF2: [4096,1024] @ [1024,512] + b
        gemm_kernel<false><<<dim3(DMOD / 64, ROWS / 128), 256>>>(
            ff1, Wo + (size_t)l * DFFV * DMOD, bo + (size_t)l * DMOD,
            ff2, ROWS, DMOD, DFFV);

        // h = LN(h + ff2); final layer writes straight to d_out
        add_ln_kernel<<<ROWS, 256>>>(h, ff2, g2 + (size_t)l * DMOD, beta2 + (size_t)l * DMOD,
                                     (l == NLAY - 1) ? out : h);
    }
}

// round 2
// speedup vs baseline: 1.3883x; 1.3883x over previous
#include <cuda_runtime.h>
#include <math.h>
#include <stdint.h>

#define NB   4
#define TT   1024
#define HH   8
#define DD   64
#define DMOD 512
#define DFFV 1024
#define NLAY 6
#define ROWS (NB * TT)   // 4096

// ---------------- scratch (static device globals; no allocation) -------------
__device__ float g_h  [ROWS * DMOD];
__device__ float g_qkv[ROWS * 3 * DMOD];
__device__ float g_att[ROWS * DMOD];
__device__ float g_ff1[ROWS * DFFV];
__device__ float g_ff2[ROWS * DMOD];

// ---------------- embedding + positional encoding ----------------------------
__global__ void embed_kernel(const int* __restrict__ x, const float* __restrict__ emb)
{
    int row = blockIdx.x;
    int t   = row & (TT - 1);
    int tok = x[row];
    const float* e = emb + (size_t)tok * DMOD;
    for (int i = threadIdx.x; i < DMOD; i += blockDim.x) {
        double expo = -2.0 * (double)(i >> 1) / (double)DMOD;
        double ang  = (double)t * pow(10000.0, expo);
        float  p    = (i & 1) ? (float)cos(ang) : (float)sin(ang);
        g_h[(size_t)row * DMOD + i] = e[i] * 22.62741699796952f + p;  // sqrt(512)
    }
}

// ---------------- TF32 tensor-core GEMM ---------------------------------------
// C[M,N] = A[M,K] @ B[K,N] + bias (+ReLU). Block tile 128x128, BK=16,
// 8 warps (4x2), warp tile 32x64, mma.sync.m16n8k8.tf32, double-buffered smem.
__device__ __forceinline__ uint32_t f2tf(float f)
{
    uint32_t r;
    asm("cvt.rna.tf32.f32 %0, %1;" : "=r"(r) : "f"(f));
    return r;
}

#define LDA 20u   // conflict-free for A-fragment access pattern
#define LDB 136u  // conflict-free for B-fragment access pattern

template<bool RELU>
__global__ __launch_bounds__(256)
void gemm_tf32(const float* __restrict__ A, const float* __restrict__ B,
               const float* __restrict__ bias, float* __restrict__ C,
               int M, int N, int K)
{
    __shared__ uint32_t As[2][128 * LDA];
    __shared__ uint32_t Bs[2][16 * LDB];

    const int tid  = threadIdx.x;
    const int bm   = blockIdx.y * 128;
    const int bn   = blockIdx.x * 128;

    // global-load assignment: A 128x16 (2 float4/thread), B 16x128 (2 float4/thread)
    const int am = tid >> 1, ak = (tid & 1) * 8;
    const int bk = tid >> 4, bcol = (tid & 15) * 8;
    const float* Aptr = A + (size_t)(bm + am) * K + ak;
    const float* Bptr = B + (size_t)bk * N + bn + bcol;

    const int warp = tid >> 5, lane = tid & 31;
    const int gid  = lane >> 2, tig = lane & 3;
    const int wm   = (warp & 3) * 32;
    const int wn   = (warp >> 2) * 64;

    float c[2][8][4];
#pragma unroll
    for (int mt = 0; mt < 2; ++mt)
#pragma unroll
        for (int nt = 0; nt < 8; ++nt)
#pragma unroll
            for (int j = 0; j < 4; ++j) c[mt][nt][j] = 0.f;

    const int nIter = K >> 4;

    // prologue: load tile 0
    float4 ra0 = *(const float4*)(Aptr);
    float4 ra1 = *(const float4*)(Aptr + 4);
    float4 rb0 = *(const float4*)(Bptr);
    float4 rb1 = *(const float4*)(Bptr + 4);
    {
        uint32_t* ad = &As[0][am * LDA + ak];
        ad[0] = f2tf(ra0.x); ad[1] = f2tf(ra0.y); ad[2] = f2tf(ra0.z); ad[3] = f2tf(ra0.w);
        ad[4] = f2tf(ra1.x); ad[5] = f2tf(ra1.y); ad[6] = f2tf(ra1.z); ad[7] = f2tf(ra1.w);
        uint32_t* bd = &Bs[0][bk * LDB + bcol];
        bd[0] = f2tf(rb0.x); bd[1] = f2tf(rb0.y); bd[2] = f2tf(rb0.z); bd[3] = f2tf(rb0.w);
        bd[4] = f2tf(rb1.x); bd[5] = f2tf(rb1.y); bd[6] = f2tf(rb1.z); bd[7] = f2tf(rb1.w);
    }
    __syncthreads();

    for (int it = 0; it < nIter; ++it) {
        const int cur = it & 1;
        const bool more = (it + 1 < nIter);
        if (more) {
            const float* Ap = Aptr + (it + 1) * 16;
            const float* Bp = Bptr + (size_t)(it + 1) * 16 * N;
            ra0 = *(const float4*)(Ap);
            ra1 = *(const float4*)(Ap + 4);
            rb0 = *(const float4*)(Bp);
            rb1 = *(const float4*)(Bp + 4);
        }

        const uint32_t* Ac = As[cur];
        const uint32_t* Bc = Bs[cur];
#pragma unroll
        for (int ks = 0; ks < 2; ++ks) {
            const int kb = ks * 8;
            uint32_t a[2][4], b[8][2];
#pragma unroll
            for (int mt = 0; mt < 2; ++mt) {
                const int r = wm + mt * 16 + gid;
                a[mt][0] = Ac[(uint32_t)r * LDA + kb + tig];
                a[mt][1] = Ac[(uint32_t)(r + 8) * LDA + kb + tig];
                a[mt][2] = Ac[(uint32_t)r * LDA + kb + tig + 4];
                a[mt][3] = Ac[(uint32_t)(r + 8) * LDA + kb + tig + 4];
            }
#pragma unroll
            for (int nt = 0; nt < 8; ++nt) {
                const int col = wn + nt * 8 + gid;
                b[nt][0] = Bc[(uint32_t)(kb + tig) * LDB + col];
                b[nt][1] = Bc[(uint32_t)(kb + tig + 4) * LDB + col];
            }
#pragma unroll
            for (int mt = 0; mt < 2; ++mt)
#pragma unroll
                for (int nt = 0; nt < 8; ++nt) {
                    asm volatile(
                        "mma.sync.aligned.m16n8k8.row.col.f32.tf32.tf32.f32 "
                        "{%0,%1,%2,%3}, {%4,%5,%6,%7}, {%8,%9}, {%0,%1,%2,%3};"
                        : "+f"(c[mt][nt][0]), "+f"(c[mt][nt][1]),
                          "+f"(c[mt][nt][2]), "+f"(c[mt][nt][3])
                        : "r"(a[mt][0]), "r"(a[mt][1]), "r"(a[mt][2]), "r"(a[mt][3]),
                          "r"(b[nt][0]), "r"(b[nt][1]));
                }
        }

        if (more) {
            const int nxt = cur ^ 1;
            uint32_t* ad = &As[nxt][am * LDA + ak];
            ad[0] = f2tf(ra0.x); ad[1] = f2tf(ra0.y); ad[2] = f2tf(ra0.z); ad[3] = f2tf(ra0.w);
            ad[4] = f2tf(ra1.x); ad[5] = f2tf(ra1.y); ad[6] = f2tf(ra1.z); ad[7] = f2tf(ra1.w);
            uint32_t* bd = &Bs[nxt][bk * LDB + bcol];
            bd[0] = f2tf(rb0.x); bd[1] = f2tf(rb0.y); bd[2] = f2tf(rb0.z); bd[3] = f2tf(rb0.w);
            bd[4] = f2tf(rb1.x); bd[5] = f2tf(rb1.y); bd[6] = f2tf(rb1.z); bd[7] = f2tf(rb1.w);
            __syncthreads();
        }
    }

    // epilogue: defined mma.sync C layout -> bias(+ReLU) -> float2 stores
#pragma unroll
    for (int mt = 0; mt < 2; ++mt) {
        const int row0 = bm + wm + mt * 16 + gid;
#pragma unroll
        for (int nt = 0; nt < 8; ++nt) {
            const int coln = bn + wn + nt * 8 + 2 * tig;
            const float2 bv = *(const float2*)(bias + coln);
            float2 v0, v1;
            v0.x = c[mt][nt][0] + bv.x; v0.y = c[mt][nt][1] + bv.y;
            v1.x = c[mt][nt][2] + bv.x; v1.y = c[mt][nt][3] + bv.y;
            if (RELU) {
                v0.x = fmaxf(v0.x, 0.f); v0.y = fmaxf(v0.y, 0.f);
                v1.x = fmaxf(v1.x, 0.f); v1.y = fmaxf(v1.y, 0.f);
            }
            *(float2*)(C + (size_t)row0 * N + coln)       = v0;
            *(float2*)(C + (size_t)(row0 + 8) * N + coln) = v1;
        }
    }
}

// ---------------- flash-style causal attention --------------------------------
__global__ __launch_bounds__(128)
void attn_kernel()
{
    __shared__ float Ks[64][64];
    __shared__ float Vs[64][64];

    int tid = threadIdx.x;
    int nh  = blockIdx.y;
    int n   = nh >> 3;
    int hh  = nh & 7;
    int qrow = blockIdx.x * 128 + tid;

    const size_t base_nk = (size_t)n * TT * 1536 + hh * 192;

    float4 qq[16];
    {
        const float* qp = g_qkv + base_nk + (size_t)qrow * 1536;
#pragma unroll
        for (int d4 = 0; d4 < 16; ++d4) {
            qq[d4].x = qp[(d4 * 4 + 0) * 3] * 0.125f;
            qq[d4].y = qp[(d4 * 4 + 1) * 3] * 0.125f;
            qq[d4].z = qp[(d4 * 4 + 2) * 3] * 0.125f;
            qq[d4].w = qp[(d4 * 4 + 3) * 3] * 0.125f;
        }
    }
    float4 oo[16];
#pragma unroll
    for (int d4 = 0; d4 < 16; ++d4) oo[d4] = make_float4(0.f, 0.f, 0.f, 0.f);
    float mval = -INFINITY, lsum = 0.f;

    int ntiles = blockIdx.x * 2 + 2;

#pragma unroll 1
    for (int kt = 0; kt < ntiles; ++kt) {
        __syncthreads();
#pragma unroll
        for (int i = 0; i < 32; ++i) {
            int idx = tid + i * 128;
            int j = idx >> 6, d = idx & 63;
            const float* kvp = g_qkv + base_nk + (size_t)(kt * 64 + j) * 1536 + d * 3;
            Ks[j][d] = kvp[1];
            Vs[j][d] = kvp[2];
        }
        __syncthreads();

        if (kt * 64 <= qrow) {
#pragma unroll 1
            for (int half = 0; half < 2; ++half) {
                int j0 = half * 32;
                float s[32];
                float tmax = -INFINITY;
#pragma unroll
                for (int j = 0; j < 32; ++j) {
                    const float4* kr = (const float4*)(&Ks[j0 + j][0]);
                    float a = 0.f;
#pragma unroll
                    for (int d4 = 0; d4 < 16; ++d4) {
                        float4 kv = kr[d4];
                        a = fmaf(qq[d4].x, kv.x, a);
                        a = fmaf(qq[d4].y, kv.y, a);
                        a = fmaf(qq[d4].z, kv.z, a);
                        a = fmaf(qq[d4].w, kv.w, a);
                    }
                    s[j] = ((kt * 64 + j0 + j) <= qrow) ? a : -INFINITY;
                    tmax = fmaxf(tmax, s[j]);
                }
                if (tmax > -INFINITY) {
                    float newm = fmaxf(mval, tmax);
                    float corr = expf(mval - newm);
                    lsum *= corr;
#pragma unroll
                    for (int d4 = 0; d4 < 16; ++d4) {
                        oo[d4].x *= corr; oo[d4].y *= corr;
                        oo[d4].z *= corr; oo[d4].w *= corr;
                    }
#pragma unroll
                    for (int j = 0; j < 32; ++j) {
                        float p = expf(s[j] - newm);
                        lsum += p;
                        const float4* vr = (const float4*)(&Vs[j0 + j][0]);
#pragma unroll
                        for (int d4 = 0; d4 < 16; ++d4) {
                            float4 vv = vr[d4];
                            oo[d4].x = fmaf(p, vv.x, oo[d4].x);
                            oo[d4].y = fmaf(p, vv.y, oo[d4].y);
                            oo[d4].z = fmaf(p, vv.z, oo[d4].z);
                            oo[d4].w = fmaf(p, vv.w, oo[d4].w);
                        }
                    }
                    mval = newm;
                }
            }
        }
    }

    float inv = 1.f / lsum;
    float* op = g_att + ((size_t)(n * TT + qrow)) * DMOD + hh * DD;
#pragma unroll
    for (int d4 = 0; d4 < 16; ++d4) {
        float4 v;
        v.x = oo[d4].x * inv; v.y = oo[d4].y * inv;
        v.z = oo[d4].z * inv; v.w = oo[d4].w * inv;
        *(float4*)(op + d4 * 4) = v;
    }
}

// ---------------- fused residual add + LayerNorm ------------------------------
__global__ __launch_bounds__(256)
void add_ln_kernel(const float* __restrict__ a, const float* __restrict__ b,
                   const float* __restrict__ gamma, const float* __restrict__ beta,
                   float* __restrict__ out)
{
    int row = blockIdx.x;
    int tid = threadIdx.x;
    const float* ar = a + (size_t)row * DMOD;
    const float* br = b + (size_t)row * DMOD;

    float x0 = ar[tid]       + br[tid];
    float x1 = ar[tid + 256] + br[tid + 256];

    float sum = x0 + x1;
    float sq  = x0 * x0 + x1 * x1;
#pragma unroll
    for (int off = 16; off; off >>= 1) {
        sum += __shfl_xor_sync(0xffffffffu, sum, off);
        sq  += __shfl_xor_sync(0xffffffffu, sq,  off);
    }
    __shared__ float s1[8], s2[8];
    int wid = tid >> 5, lane = tid & 31;
    if (lane == 0) { s1[wid] = sum; s2[wid] = sq; }
    __syncthreads();
    float S = 0.f, Q = 0.f;
#pragma unroll
    for (int i = 0; i < 8; ++i) { S += s1[i]; Q += s2[i]; }

    float mean = S * (1.f / DMOD);
    float var  = Q * (1.f / DMOD) - mean * mean;
    float rstd = 1.f / sqrtf(var + 1e-3f);

    out[(size_t)row * DMOD + tid]       = gamma[tid]       * (x0 - mean) * rstd + beta[tid];
    out[(size_t)row * DMOD + tid + 256] = gamma[tid + 256] * (x1 - mean) * rstd + beta[tid + 256];
}

// ---------------- launch ------------------------------------------------------
extern "C" void kernel_launch(void* const* d_in, const int* in_sizes, int n_in,
                              void* d_out, int out_size)
{
    const int*   x     = (const int*)  d_in[0];
    const float* emb   = (const float*)d_in[1];
    const float* Wqkv  = (const float*)d_in[2];
    const float* bqkv  = (const float*)d_in[3];
    const float* Wff   = (const float*)d_in[4];
    const float* bff   = (const float*)d_in[5];
    const float* Wo    = (const float*)d_in[6];
    const float* bo    = (const float*)d_in[7];
    const float* g1    = (const float*)d_in[8];
    const float* beta1 = (const float*)d_in[9];
    const float* g2    = (const float*)d_in[10];
    const float* beta2 = (const float*)d_in[11];
    float* out = (float*)d_out;

    float *h, *qkv, *att, *ff1, *ff2;
    cudaGetSymbolAddress((void**)&h,   g_h);
    cudaGetSymbolAddress((void**)&qkv, g_qkv);
    cudaGetSymbolAddress((void**)&att, g_att);
    cudaGetSymbolAddress((void**)&ff1, g_ff1);
    cudaGetSymbolAddress((void**)&ff2, g_ff2);

    embed_kernel<<<ROWS, 128>>>(x, emb);

    for (int l = 0; l < NLAY; ++l) {
        // QKV projection: [4096,512] @ [512,1536] + b
        gemm_tf32<false><<<dim3(1536 / 128, ROWS / 128), 256>>>(
            h, Wqkv + (size_t)l * DMOD * 3 * DMOD, bqkv + (size_t)l * 3 * DMOD,
            qkv, ROWS, 3 * DMOD, DMOD);

        attn_kernel<<<dim3(TT / 128, NB * HH), 128>>>();

        add_ln_kernel<<<ROWS, 256>>>(h, att, g1 + (size_t)l * DMOD, beta1 + (size_t)l * DMOD, h);

        // FF1: relu([4096,512] @ [512,1024] + b)
        gemm_tf32<true><<<dim3(DFFV / 128, ROWS / 128), 256>>>(
            h, Wff + (size_t)l * DMOD * DFFV, bff + (size_t)l * DFFV,
            ff1, ROWS, DFFV, DMOD);

        // FF2: [4096,1024] @ [1024,512] + b
        gemm_tf32<false><<<dim3(DMOD / 128, ROWS / 128), 256>>>(
            ff1, Wo + (size_t)l * DFFV * DMOD, bo + (size_t)l * DMOD,
            ff2, ROWS, DMOD, DFFV);

        add_ln_kernel<<<ROWS, 256>>>(h, ff2, g2 + (size_t)l * DMOD, beta2 + (size_t)l * DMOD,
                                     (l == NLAY - 1) ? out : h);
    }
}